// round 15
// baseline (speedup 1.0000x reference)
#include <cuda_runtime.h>

// ASG loss: FCC (free-running) - FAC (forced alignment), mean over batch.
// B=128, T=1024, N=128, S=256.
// 384 threads: warps 0-3 FAC (2 positions/thread, own barrier),
// warps 4-11 FCC (thread pair (2r,2r+1) computes row r; each half the
// i-range; combined via shfl_xor(1)). 2 FCC warps per SMSP hide latency.
#define BB 128
#define TT 1024
#define NN 128
#define SS 256
#define NEGF (-1e30f)
#define NTH 384

__device__ float g_loss[BB];

struct __align__(16) Smem {
    float Pb[2][NN];      // ping-pong P = exp(alpha - sig); u(t) == log(Pb[t][0])
    float bbuf[2][SS];    // FAC beta double buffer
    int   tg[SS];
    float alphaS[NN];     // final alpha staging
    float red[4];
    float red2[4];
};

__device__ __forceinline__ unsigned long long pack2(float lo, float hi) {
    unsigned long long r;
    asm("mov.b64 %0, {%1, %2};" : "=l"(r) : "f"(lo), "f"(hi));
    return r;
}
__device__ __forceinline__ void unpack2(float& lo, float& hi, unsigned long long v) {
    asm("mov.b64 {%0, %1}, %2;" : "=f"(lo), "=f"(hi) : "l"(v));
}
#define FMA2(acc, a, b) \
    asm("fma.rn.f32x2 %0, %1, %2, %0;" : "+l"(acc) : "l"(a), "l"(b))
#define ADD2(d, a, b) \
    asm("add.rn.f32x2 %0, %1, %2;" : "=l"(d) : "l"(a), "l"(b))

__global__ __launch_bounds__(NTH, 1)
void asg_main(const float* __restrict__ trans,
              const float* __restrict__ x,
              const int*   __restrict__ targets,
              const int*   __restrict__ in_len,
              const int*   __restrict__ tgt_len)
{
    __shared__ Smem sm;

    const int b    = blockIdx.x;
    const int tid  = threadIdx.x;
    const int lane = tid & 31;
    const int wid  = tid >> 5;

    const int len = in_len[b];
    const float* xb = x + (size_t)b * TT * NN;

    if (tid < SS) sm.tg[tid] = targets[b * SS + tid];

    // ===== FCC init (warps 4-11): ft = tid-128, row r = ft>>1, half h = ft&1 =====
    unsigned long long E2[32];        // exp(trans[r, 64h .. 64h+64)) packed f32x2
    const int ft = tid - NN;
    const int r  = ft >> 1;
    const int h  = ft & 1;
    float xc1 = 0.f, xc2 = 0.f;       // x rows t, t+1 (register pipeline)
    float sig_run = 0.f;              // sig(t-1) entering iter t
    float alphaF = 0.f;
    if (tid >= NN) {
        const float4* tr4 =
            reinterpret_cast<const float4*>(trans + r * NN + (h << 6));
#pragma unroll
        for (int i4 = 0; i4 < 16; ++i4) {
            float4 v = tr4[i4];
            E2[2 * i4 + 0] = pack2(__expf(v.x), __expf(v.y));
            E2[2 * i4 + 1] = pack2(__expf(v.z), __expf(v.w));
        }
        float a0 = xb[r];              // alpha_r(0) = x_r(0)
        sig_run  = __ldg(&xb[0]);      // sig(0) = alpha_0(0)
        alphaF   = a0;
        xc1 = xb[NN + r];
        xc2 = xb[2 * NN + r];
        if (h == 0) sm.Pb[0][r] = __expf(a0 - sig_run);   // P(0); Pb[0][0]=1 -> u(0)=0
    }
    __syncthreads();   // tg, Pb[0] visible

    // ===== FAC init (warps 0-3): positions s0 = tid, s1 = tid + 128 =====
    float beta0 = NEGF, beta1 = NEGF;
    float st0 = 0.f, nt0 = 0.f, st1 = 0.f, nt1 = 0.f;
    int   tg0 = 0, tg1 = 0;
    float em0c = 0.f, em0n = 0.f, em1c = 0.f, em1n = 0.f;
    if (tid < NN) {
        const int s0 = tid, s1 = tid + NN;
        tg0 = sm.tg[s0];
        tg1 = sm.tg[s1];
        int p0 = (s0 == 0) ? tg0 : sm.tg[s0 - 1];
        int p1 = sm.tg[s1 - 1];
        st0 = trans[tg0 * NN + tg0];
        nt0 = trans[tg0 * NN + p0];
        st1 = trans[tg1 * NN + tg1];
        nt1 = trans[tg1 * NN + p1];
        beta0 = (s0 == 0) ? __ldg(&xb[tg0]) : NEGF;
        sm.bbuf[0][s0] = beta0;
        sm.bbuf[0][s1] = beta1;
        em0c = __ldg(&xb[NN + tg0]);
        em1c = __ldg(&xb[NN + tg1]);
        em0n = __ldg(&xb[2 * NN + tg0]);
        em1n = __ldg(&xb[2 * NN + tg1]);
    }
    __syncthreads();   // bbuf[0] visible

    if (tid >= NN) {
        // ====== FCC loop: half-row matvec, 2 warps/SMSP fill stalls ======
        float pj = 1.0f;                           // P_r(t) (h==0 lanes authoritative)
        for (int t = 1; t < len; ++t) {
            const int rd = (t - 1) & 1;
            const int wr = t & 1;

            float u_prev = __logf(sm.Pb[rd][0]);   // u(t-1); broadcast LDS + MUFU
            float K = __expf(xc1 - u_prev);        // off critical path
            float xnew = (t + 2 < TT) ? __ldg(&xb[(t + 2) * NN + r]) : 0.0f;

            unsigned long long a0 = 0ull, a1 = 0ull, a2 = 0ull, a3 = 0ull;
            const ulonglong2* P2 =
                reinterpret_cast<const ulonglong2*>(sm.Pb[rd] + (h << 6));
#pragma unroll
            for (int k = 0; k < 8; ++k) {          // 8 iters: 16 LDS.128, 32 FMA2
                ulonglong2 p01 = P2[2 * k];
                ulonglong2 p23 = P2[2 * k + 1];
                FMA2(a0, p01.x, E2[4 * k + 0]);
                FMA2(a1, p01.y, E2[4 * k + 1]);
                FMA2(a2, p23.x, E2[4 * k + 2]);
                FMA2(a3, p23.y, E2[4 * k + 3]);
            }
            unsigned long long s01, s23, sAll;
            ADD2(s01, a0, a1);
            ADD2(s23, a2, a3);
            ADD2(sAll, s01, s23);
            float lo, hi;
            unpack2(lo, hi, sAll);
            float mine = lo + hi;
            float full = mine + __shfl_xor_sync(0xffffffffu, mine, 1);

            pj = K * full;
            if (h == 0) sm.Pb[wr][r] = pj;         // tail: FMUL + STS

            sig_run += u_prev;                     // sig(t-1) -> sig(t)
            xc1 = xc2; xc2 = xnew;
            asm volatile("bar.sync 1, 256;" ::: "memory");
        }
        // alpha_r(len-1) = sig(len-1) + log P_r(len-1)
        if (len > 1) alphaF = sig_run + __logf(pj);
    } else {
        // ============ FAC loop: decoupled, own barrier ============
        const int s0 = tid, s1 = tid + NN;
        for (int t = 1; t < len; ++t) {
            const int rd = (t - 1) & 1;
            const int wr = t & 1;

            float em0n2 = 0.f, em1n2 = 0.f;
            if (t + 2 < TT) {
                em0n2 = __ldg(&xb[(t + 2) * NN + tg0]);
                em1n2 = __ldg(&xb[(t + 2) * NN + tg1]);
            }
            float bl0 = (s0 == 0) ? NEGF : sm.bbuf[rd][s0 - 1];
            float bl1 = sm.bbuf[rd][s1 - 1];

            float va0 = beta0 + st0, vb0 = bl0 + nt0;
            float mx0 = fmaxf(va0, vb0), mn0 = fminf(va0, vb0);
            beta0 = em0c + mx0 + __logf(1.0f + __expf(mn0 - mx0));
            sm.bbuf[wr][s0] = beta0;

            float va1 = beta1 + st1, vb1 = bl1 + nt1;
            float mx1 = fmaxf(va1, vb1), mn1 = fminf(va1, vb1);
            beta1 = em1c + mx1 + __logf(1.0f + __expf(mn1 - mx1));
            sm.bbuf[wr][s1] = beta1;

            em0c = em0n; em0n = em0n2;
            em1c = em1n; em1n = em1n2;
            asm volatile("bar.sync 2, 128;" ::: "memory");
        }
    }

    __syncthreads();   // join FCC + FAC

    // ---- finalize: stage alpha per row, exact LSE by warps 4-7 ----
    if (tid >= NN && h == 0) sm.alphaS[r] = alphaF;
    __syncthreads();

    if (tid >= NN && tid < 2 * NN) {   // warps 4-7, ft = 0..127
        float a = sm.alphaS[ft];
        float m = a;
        m = fmaxf(m, __shfl_xor_sync(0xffffffffu, m, 16));
        m = fmaxf(m, __shfl_xor_sync(0xffffffffu, m, 8));
        m = fmaxf(m, __shfl_xor_sync(0xffffffffu, m, 4));
        m = fmaxf(m, __shfl_xor_sync(0xffffffffu, m, 2));
        m = fmaxf(m, __shfl_xor_sync(0xffffffffu, m, 1));
        if (lane == 0) sm.red[wid - 4] = m;
    }
    __syncthreads();
    if (tid >= NN && tid < 2 * NN) {
        float a = sm.alphaS[ft];
        float Mf = fmaxf(fmaxf(sm.red[0], sm.red[1]), fmaxf(sm.red[2], sm.red[3]));
        float p = __expf(a - Mf);
        p += __shfl_xor_sync(0xffffffffu, p, 16);
        p += __shfl_xor_sync(0xffffffffu, p, 8);
        p += __shfl_xor_sync(0xffffffffu, p, 4);
        p += __shfl_xor_sync(0xffffffffu, p, 2);
        p += __shfl_xor_sync(0xffffffffu, p, 1);
        if (lane == 0) { sm.red2[wid - 4] = p; sm.red[wid - 4] = Mf; }
    }
    __syncthreads();
    if (tid == 0) {
        float ssum = sm.red2[0] + sm.red2[1] + sm.red2[2] + sm.red2[3];
        float fcc = sm.red[0] + __logf(ssum);
        int tl = tgt_len[b];
        float fac = sm.bbuf[(len - 1) & 1][tl - 1];
        g_loss[b] = fcc - fac;
    }
}

__global__ void asg_reduce(float* __restrict__ out)
{
    int t = threadIdx.x;   // 128 threads
    float v = g_loss[t];
    v += __shfl_xor_sync(0xffffffffu, v, 16);
    v += __shfl_xor_sync(0xffffffffu, v, 8);
    v += __shfl_xor_sync(0xffffffffu, v, 4);
    v += __shfl_xor_sync(0xffffffffu, v, 2);
    v += __shfl_xor_sync(0xffffffffu, v, 1);
    __shared__ float ws[4];
    if ((t & 31) == 0) ws[t >> 5] = v;
    __syncthreads();
    if (t == 0) out[0] = (ws[0] + ws[1] + ws[2] + ws[3]) * (1.0f / (float)BB);
}

extern "C" void kernel_launch(void* const* d_in, const int* in_sizes, int n_in,
                              void* d_out, int out_size)
{
    const float* trans   = (const float*)d_in[0];
    const float* x       = (const float*)d_in[1];
    const int*   targets = (const int*)d_in[2];
    const int*   in_len  = (const int*)d_in[3];
    const int*   tgt_len = (const int*)d_in[4];

    asg_main<<<BB, NTH>>>(trans, x, targets, in_len, tgt_len);
    asg_reduce<<<1, 128>>>((float*)d_out);
}

// round 17
// speedup vs baseline: 1.7343x; 1.7343x over previous
#include <cuda_runtime.h>

// ASG loss: FCC (free-running) - FAC (forced alignment), mean over batch.
// B=128, T=1024, N=128, S=256.
#define BB 128
#define TT 1024
#define NN 128
#define SS 256
#define NEGF (-1e30f)
#define NTH 256   // warps 0-3: FAC (2 positions each), warps 4-7: FCC (j = tid-128)

__device__ float g_loss[BB];

struct __align__(16) Smem {
    float Pb[2][NN];      // ping-pong P = exp(alpha - sig); u(t) == log(Pb[t][0])
    float bbuf[2][SS];    // FAC beta double buffer
    int   tg[SS];
    float red[4];
    float red2[4];
};

__device__ __forceinline__ unsigned long long pack2(float lo, float hi) {
    unsigned long long r;
    asm("mov.b64 %0, {%1, %2};" : "=l"(r) : "f"(lo), "f"(hi));
    return r;
}
__device__ __forceinline__ void unpack2(float& lo, float& hi, unsigned long long v) {
    asm("mov.b64 {%0, %1}, %2;" : "=f"(lo), "=f"(hi) : "l"(v));
}
#define FMA2(acc, a, b) \
    asm("fma.rn.f32x2 %0, %1, %2, %0;" : "+l"(acc) : "l"(a), "l"(b))
#define ADD2(d, a, b) \
    asm("add.rn.f32x2 %0, %1, %2;" : "=l"(d) : "l"(a), "l"(b))

// One FCC time step with literal read/write buffer indices.
#define FCC_STEP(RD, WR, TCUR)                                                 \
    {                                                                          \
        float u_prev = __logf(sm.Pb[RD][0]);                                   \
        float K = __expf(xc1 - u_prev);                                        \
        int tp = (TCUR) + 2; if (tp > TT - 1) tp = TT - 1;                     \
        float xnew = __ldg(&xb[tp * NN + j]);                                  \
        unsigned long long a0 = 0ull, a1 = 0ull, a2 = 0ull, a3 = 0ull;         \
        const ulonglong2* P2 = reinterpret_cast<const ulonglong2*>(sm.Pb[RD]); \
        _Pragma("unroll")                                                      \
        for (int k = 0; k < 16; ++k) {                                         \
            ulonglong2 p01 = P2[2 * k];                                        \
            ulonglong2 p23 = P2[2 * k + 1];                                    \
            FMA2(a0, p01.x, E2[4 * k + 0]);                                    \
            FMA2(a1, p01.y, E2[4 * k + 1]);                                    \
            FMA2(a2, p23.x, E2[4 * k + 2]);                                    \
            FMA2(a3, p23.y, E2[4 * k + 3]);                                    \
        }                                                                      \
        unsigned long long s01, s23, sAll;                                     \
        ADD2(s01, a0, a1);                                                     \
        ADD2(s23, a2, a3);                                                     \
        ADD2(sAll, s01, s23);                                                  \
        float lo, hi;                                                          \
        unpack2(lo, hi, sAll);                                                 \
        float acc = lo + hi;                                                   \
        pj = K * acc;                                                          \
        sm.Pb[WR][j] = pj;                                                     \
        sig_run += u_prev;                                                     \
        xc1 = xc2; xc2 = xnew;                                                 \
        asm volatile("bar.sync 1, 128;" ::: "memory");                         \
    }

// FAC position-0 half step (always active).
#define FAC_S0(RD, WR, TCUR)                                                   \
    {                                                                          \
        int tp = (TCUR) + 2; if (tp > TT - 1) tp = TT - 1;                     \
        float em0n2 = __ldg(&xb[tp * NN + tg0]);                               \
        float bl0 = (s0 == 0) ? NEGF : sm.bbuf[RD][s0 - 1];                    \
        float va0 = beta0 + st0, vb0 = bl0 + nt0;                              \
        float mx0 = fmaxf(va0, vb0), mn0 = fminf(va0, vb0);                    \
        beta0 = em0c + mx0 + __logf(1.0f + __expf(mn0 - mx0));                 \
        sm.bbuf[WR][s0] = beta0;                                               \
        em0c = em0n; em0n = em0n2;                                             \
    }

// FAC position-1 half step.
#define FAC_S1(RD, WR, TCUR)                                                   \
    {                                                                          \
        int tp = (TCUR) + 2; if (tp > TT - 1) tp = TT - 1;                     \
        float em1n2 = __ldg(&xb[tp * NN + tg1]);                               \
        float bl1 = sm.bbuf[RD][s1 - 1];                                       \
        float va1 = beta1 + st1, vb1 = bl1 + nt1;                              \
        float mx1 = fmaxf(va1, vb1), mn1 = fminf(va1, vb1);                    \
        beta1 = em1c + mx1 + __logf(1.0f + __expf(mn1 - mx1));                 \
        sm.bbuf[WR][s1] = beta1;                                               \
        em1c = em1n; em1n = em1n2;                                             \
    }

__global__ __launch_bounds__(NTH, 1)
void asg_main(const float* __restrict__ trans,
              const float* __restrict__ x,
              const int*   __restrict__ targets,
              const int*   __restrict__ in_len,
              const int*   __restrict__ tgt_len)
{
    __shared__ Smem sm;

    const int b    = blockIdx.x;
    const int tid  = threadIdx.x;
    const int lane = tid & 31;
    const int wid  = tid >> 5;

    const int len = in_len[b];
    const float* xb = x + (size_t)b * TT * NN;

    sm.tg[tid] = targets[b * SS + tid];

    // =========== FCC init (warps 4-7, j = tid - 128) ===========
    unsigned long long E2[NN / 2];
    const int j = tid - NN;
    float xc1 = 0.f, xc2 = 0.f;       // x rows t, t+1 (register pipeline)
    float sig_run = 0.f;              // sig(t-1) entering iter t
    float alphaF = 0.f;               // final alpha (reconstructed)
    if (tid >= NN) {
        const float4* tr4 = reinterpret_cast<const float4*>(trans + j * NN);
#pragma unroll
        for (int i4 = 0; i4 < NN / 4; ++i4) {
            float4 v = tr4[i4];
            E2[2 * i4 + 0] = pack2(__expf(v.x), __expf(v.y));
            E2[2 * i4 + 1] = pack2(__expf(v.z), __expf(v.w));
        }
        float a0 = xb[j];              // alpha_j(0) = x_j(0)
        sig_run  = __ldg(&xb[0]);      // sig(0) = alpha_0(0)
        alphaF   = a0;
        xc1 = xb[NN + j];
        xc2 = xb[2 * NN + j];
        sm.Pb[0][j] = __expf(a0 - sig_run);   // P(0); Pb[0][0] = 1 -> u(0) = 0
    }
    __syncthreads();   // tg, Pb[0] visible

    // =========== FAC init (warps 0-3): positions s0 = tid, s1 = tid + 128 ===========
    float beta0 = NEGF, beta1 = NEGF;
    float st0 = 0.f, nt0 = 0.f, st1 = 0.f, nt1 = 0.f;
    int   tg0 = 0, tg1 = 0;
    float em0c = 0.f, em0n = 0.f, em1c = 0.f, em1n = 0.f;
    int   tl = 0;
    if (tid < NN) {
        const int s0 = tid, s1 = tid + NN;
        tl  = tgt_len[b];
        tg0 = sm.tg[s0];
        tg1 = sm.tg[s1];
        int p0 = (s0 == 0) ? tg0 : sm.tg[s0 - 1];
        int p1 = sm.tg[s1 - 1];
        st0 = trans[tg0 * NN + tg0];
        nt0 = trans[tg0 * NN + p0];
        st1 = trans[tg1 * NN + tg1];
        nt1 = trans[tg1 * NN + p1];
        beta0 = (s0 == 0) ? __ldg(&xb[tg0]) : NEGF;
        sm.bbuf[0][s0] = beta0;
        sm.bbuf[0][s1] = beta1;
        em0c = __ldg(&xb[NN + tg0]);
        em1c = __ldg(&xb[NN + tg1]);
        em0n = __ldg(&xb[2 * NN + tg0]);
        em1n = __ldg(&xb[2 * NN + tg1]);
    }
    __syncthreads();   // bbuf[0] visible

    if (tid >= NN) {
        // ====== FCC loop: 2x unrolled, bodies identical to the 217.6us step ======
        float pj = 1.0f;                           // P_j(t); STS source
        int t = 1;                                 // t stays odd at pair heads
        for (; t + 1 < len; t += 2) {
            FCC_STEP(0, 1, t)                      // odd t:  rd=0, wr=1
            FCC_STEP(1, 0, t + 1)                  // even:   rd=1, wr=0
        }
        if (t < len) {
            FCC_STEP(0, 1, t)                      // leftover odd step
        }
        // alpha_j(len-1) = sig(len-1) + log P_j(len-1)
        if (len > 1) alphaF = sig_run + __logf(pj);
    } else {
        // ====== FAC loop: warp-uniform tail skip (positions >= tl are dead) ======
        const int s0 = tid, s1 = tid + NN;
        const bool skip1 = (tl <= NN + (wid << 5));   // whole s1-range of this warp dead
        if (skip1) {
            for (int t = 1; t < len; ++t) {
                const int rd = (t - 1) & 1;
                const int wr = t & 1;
                FAC_S0(rd, wr, t)
                asm volatile("bar.sync 2, 128;" ::: "memory");
            }
        } else {
            for (int t = 1; t < len; ++t) {
                const int rd = (t - 1) & 1;
                const int wr = t & 1;
                FAC_S0(rd, wr, t)
                FAC_S1(rd, wr, t)
                asm volatile("bar.sync 2, 128;" ::: "memory");
            }
        }
    }

    __syncthreads();   // join FCC + FAC

    // ---- finalize FCC: exact logsumexp over alphaF (warps 4-7) ----
    if (tid >= NN) {
        float m = alphaF;
        m = fmaxf(m, __shfl_xor_sync(0xffffffffu, m, 16));
        m = fmaxf(m, __shfl_xor_sync(0xffffffffu, m, 8));
        m = fmaxf(m, __shfl_xor_sync(0xffffffffu, m, 4));
        m = fmaxf(m, __shfl_xor_sync(0xffffffffu, m, 2));
        m = fmaxf(m, __shfl_xor_sync(0xffffffffu, m, 1));
        if (lane == 0) sm.red[wid - 4] = m;
    }
    __syncthreads();
    if (tid >= NN) {
        float Mf = fmaxf(fmaxf(sm.red[0], sm.red[1]), fmaxf(sm.red[2], sm.red[3]));
        float p = __expf(alphaF - Mf);
        p += __shfl_xor_sync(0xffffffffu, p, 16);
        p += __shfl_xor_sync(0xffffffffu, p, 8);
        p += __shfl_xor_sync(0xffffffffu, p, 4);
        p += __shfl_xor_sync(0xffffffffu, p, 2);
        p += __shfl_xor_sync(0xffffffffu, p, 1);
        if (lane == 0) { sm.red2[wid - 4] = p; sm.red[wid - 4] = Mf; }
    }
    __syncthreads();
    if (tid == 0) {
        float ssum = sm.red2[0] + sm.red2[1] + sm.red2[2] + sm.red2[3];
        float fcc = sm.red[0] + __logf(ssum);
        float fac = sm.bbuf[(len - 1) & 1][tl - 1];
        g_loss[b] = fcc - fac;
    }
}

__global__ void asg_reduce(float* __restrict__ out)
{
    int t = threadIdx.x;   // 128 threads
    float v = g_loss[t];
    v += __shfl_xor_sync(0xffffffffu, v, 16);
    v += __shfl_xor_sync(0xffffffffu, v, 8);
    v += __shfl_xor_sync(0xffffffffu, v, 4);
    v += __shfl_xor_sync(0xffffffffu, v, 2);
    v += __shfl_xor_sync(0xffffffffu, v, 1);
    __shared__ float ws[4];
    if ((t & 31) == 0) ws[t >> 5] = v;
    __syncthreads();
    if (t == 0) out[0] = (ws[0] + ws[1] + ws[2] + ws[3]) * (1.0f / (float)BB);
}

extern "C" void kernel_launch(void* const* d_in, const int* in_sizes, int n_in,
                              void* d_out, int out_size)
{
    const float* trans   = (const float*)d_in[0];
    const float* x       = (const float*)d_in[1];
    const int*   targets = (const int*)d_in[2];
    const int*   in_len  = (const int*)d_in[3];
    const int*   tgt_len = (const int*)d_in[4];

    asg_main<<<BB, NTH>>>(trans, x, targets, in_len, tgt_len);
    asg_reduce<<<1, 128>>>((float*)d_out);
}